// round 8
// baseline (speedup 1.0000x reference)
#include <cuda_runtime.h>

#define NNODES 100000
#define NEDGES 1600000
#define NREL 4

// Scratch (node-major S: S[r][node][DIN])
__device__ __align__(16) float g_S1[NREL * NNODES * 16];  // 25.6 MB
__device__ __align__(16) float g_S2[NREL * NNODES * 16];  // 25.6 MB
__device__ __align__(16) float g_S3[NREL * NNODES * 32];  // 51.2 MB
__device__ int   g_cnt[NREL * NNODES];                    // 1.6 MB
__device__ __align__(16) float g_h1[NNODES * 16];
__device__ __align__(16) float g_h2[NNODES * 32];

typedef unsigned long long ull;

__device__ __forceinline__ void ffma2(ull& acc, ull a, ull b) {
    asm("fma.rn.f32x2 %0, %1, %2, %0;" : "+l"(acc) : "l"(a), "l"(b));
}
__device__ __forceinline__ ull bcast2(float v) {
    ull r;
    unsigned int u = __float_as_uint(v);
    asm("mov.b64 %0, {%1, %1};" : "=l"(r) : "r"(u));
    return r;
}

// ---------------------------------------------------------------------------
// Scatter: S[r, dst, :] += h[src, :] via RED.v4 (node-major S).
// ---------------------------------------------------------------------------
template <int DIN, bool COUNT>
__global__ void scatter_kernel(const float* __restrict__ h,
                               const int* __restrict__ src,
                               const int* __restrict__ dst,
                               const int* __restrict__ et,
                               float* __restrict__ S,
                               int* __restrict__ cnt, int n, int e) {
    constexpr int CH = DIN / 4;
    int t = blockIdx.x * blockDim.x + threadIdx.x;
    int ed = t / CH;
    int c  = t - ed * CH;
    if (ed >= e) return;
    int s = __ldg(src + ed);
    int d = __ldg(dst + ed);
    int r = __ldg(et + ed);
    const float4 v = *reinterpret_cast<const float4*>(h + (size_t)s * DIN + c * 4);
    float* p = S + ((size_t)r * n + d) * DIN + c * 4;
    asm volatile("red.global.add.v4.f32 [%0], {%1,%2,%3,%4};"
                 :: "l"(p), "f"(v.x), "f"(v.y), "f"(v.z), "f"(v.w)
                 : "memory");
    if (COUNT && c == 0) atomicAdd(cnt + r * n + d, 1);
}

// ---------------------------------------------------------------------------
// Combine (persistent, SMEM-staged inputs):
//   out[i] = bias + x[i]@root + sum_r (S_r,i/max(cnt,1)) @ W_r
// Per tile: cooperatively bulk-load the NPB nodes' inputs (5 contiguous
// node-major regions -> fully coalesced, high MLP) into padded smem rows,
// sync, then compute entirely from smem (broadcast weight LDS + conflict-free
// input LDS). Global latency paid once per tile, not per inner step.
// ---------------------------------------------------------------------------
template <int DIN, int DOUT, int SPLIT, int NT, bool RELU>
__global__ void __launch_bounds__(256)
combine_kernel(const float* __restrict__ xin,   // [n, DIN]
               const float* __restrict__ S,     // [R, n, DIN]
               const int* __restrict__ cnt,
               const float* __restrict__ W,     // [R, DIN, DOUT]
               const float* __restrict__ root,  // [DIN, DOUT]
               const float* __restrict__ bias,  // [DOUT]
               float* __restrict__ out, int n, int tiles) {
    constexpr int COLS = 8;
    static_assert(DOUT / SPLIT == COLS, "COLS mismatch");
    constexpr int NG   = 256 / SPLIT;      // node-groups per block
    constexpr int NPB  = NG * NT;          // nodes per tile
    constexpr int CH   = DIN / 4;
    constexpr int ROW  = 5 * DIN;          // floats per node (x + 4 rels)
    constexpr int ROWP = ROW + 4;          // padded stride (16B-aligned)
    constexpr int WSZ  = 5 * DIN * DOUT;

    extern __shared__ float smem[];
    float* swt = smem;                     // weights
    float* sin = smem + WSZ;               // input tile [NPB][ROWP]

    const int tid = threadIdx.x;
    {   // stage weights once per block
        const float4* r4 = reinterpret_cast<const float4*>(root);
        const float4* w4 = reinterpret_cast<const float4*>(W);
        float4* d4 = reinterpret_cast<float4*>(swt);
        for (int i = tid; i < DIN * DOUT / 4; i += 256) d4[i] = __ldg(r4 + i);
        for (int i = tid; i < NREL * DIN * DOUT / 4; i += 256)
            d4[DIN * DOUT / 4 + i] = __ldg(w4 + i);
    }

    const int ng = tid / SPLIT;
    const int sp = tid % SPLIT;
    const float* wbase = swt + sp * COLS;
    const ull* bb = reinterpret_cast<const ull*>(bias + sp * COLS);

    for (int t = blockIdx.x; t < tiles; t += gridDim.x) {
        const int tstart = t * NPB;

        // Per-node scale factors (LDG early, overlaps with staging)
        int nodev[NT];
        bool valid[NT];
        float sc[NT][5];
#pragma unroll
        for (int i = 0; i < NT; i++) {
            int nd = tstart + ng + i * NG;
            valid[i] = nd < n;
            nodev[i] = valid[i] ? nd : 0;
            sc[i][0] = 1.0f;
#pragma unroll
            for (int r = 0; r < NREL; r++) {
                int c = __ldg(cnt + r * n + nodev[i]);
                sc[i][r + 1] = 1.0f / (float)(c > 1 ? c : 1);
            }
        }

        __syncthreads();   // previous tile's smem readers done
        {   // cooperative input staging: 5 contiguous node-major regions
            const int nload = min(NPB, n - tstart);
            const int cnt4 = nload * CH;
            const float4* src0 =
                reinterpret_cast<const float4*>(xin + (size_t)tstart * DIN);
            for (int i = tid; i < cnt4; i += 256) {
                int local = i / CH, c = i - local * CH;
                *reinterpret_cast<float4*>(sin + local * ROWP + c * 4) =
                    __ldg(src0 + i);
            }
#pragma unroll
            for (int r = 0; r < NREL; r++) {
                const float4* srcr = reinterpret_cast<const float4*>(
                    S + ((size_t)r * n + tstart) * DIN);
                for (int i = tid; i < cnt4; i += 256) {
                    int local = i / CH, c = i - local * CH;
                    *reinterpret_cast<float4*>(
                        sin + local * ROWP + (r + 1) * DIN + c * 4) =
                        __ldg(srcr + i);
                }
            }
        }
        __syncthreads();

        ull acc[NT][4];
#pragma unroll
        for (int i = 0; i < NT; i++)
#pragma unroll
            for (int j = 0; j < 4; j++) acc[i][j] = bb[j];

        const float* in0 = sin + ng * ROWP;

#pragma unroll
        for (int rb = 0; rb < 5; rb++) {
#pragma unroll
            for (int c4 = 0; c4 < CH; c4++) {
                ulonglong2 w[4][2];
#pragma unroll
                for (int k = 0; k < 4; k++) {
                    const ulonglong2* wp = reinterpret_cast<const ulonglong2*>(
                        wbase + (rb * DIN + c4 * 4 + k) * DOUT);
                    w[k][0] = wp[0];
                    w[k][1] = wp[1];
                }
#pragma unroll
                for (int i = 0; i < NT; i++) {
                    const float4 v = *reinterpret_cast<const float4*>(
                        in0 + i * NG * ROWP + rb * DIN + c4 * 4);
                    const float s0 = sc[i][rb];
                    const float vv[4] = {v.x * s0, v.y * s0, v.z * s0, v.w * s0};
#pragma unroll
                    for (int k = 0; k < 4; k++) {
                        const ull v2 = bcast2(vv[k]);
                        ffma2(acc[i][0], v2, w[k][0].x);
                        ffma2(acc[i][1], v2, w[k][0].y);
                        ffma2(acc[i][2], v2, w[k][1].x);
                        ffma2(acc[i][3], v2, w[k][1].y);
                    }
                }
            }
        }

#pragma unroll
        for (int i = 0; i < NT; i++) {
            if (!valid[i]) continue;
            float* op = out + (size_t)nodev[i] * DOUT + sp * COLS;
#pragma unroll
            for (int j = 0; j < 4; j++) {
                float2 f = *reinterpret_cast<float2*>(&acc[i][j]);
                if (RELU) {
                    f.x = fmaxf(f.x, 0.0f);
                    f.y = fmaxf(f.y, 0.0f);
                }
                reinterpret_cast<float2*>(op)[j] = f;
            }
        }
    }
}

// ---------------------------------------------------------------------------
// Launcher
// ---------------------------------------------------------------------------
extern "C" void kernel_launch(void* const* d_in, const int* in_sizes, int n_in,
                              void* d_out, int out_size) {
    const float* x     = (const float*)d_in[0];
    const int*   ei    = (const int*)d_in[1];   // [2, E]: src then dst
    const int*   et    = (const int*)d_in[2];
    const float* W1    = (const float*)d_in[3];
    const float* root1 = (const float*)d_in[4];
    const float* b1    = (const float*)d_in[5];
    const float* W2    = (const float*)d_in[6];
    const float* root2 = (const float*)d_in[7];
    const float* b2    = (const float*)d_in[8];
    const float* W3    = (const float*)d_in[9];
    const float* root3 = (const float*)d_in[10];
    const float* b3    = (const float*)d_in[11];
    float* out = (float*)d_out;

    const int n = in_sizes[0] / 16;
    const int e = in_sizes[2];
    const int* src = ei;
    const int* dst = ei + e;

    float *pS1, *pS2, *pS3, *ph1, *ph2;
    int* pcnt;
    cudaGetSymbolAddress((void**)&pS1, g_S1);
    cudaGetSymbolAddress((void**)&pS2, g_S2);
    cudaGetSymbolAddress((void**)&pS3, g_S3);
    cudaGetSymbolAddress((void**)&pcnt, g_cnt);
    cudaGetSymbolAddress((void**)&ph1, g_h1);
    cudaGetSymbolAddress((void**)&ph2, g_h2);

    cudaMemsetAsync(pS1, 0, sizeof(float) * NREL * NNODES * 16);
    cudaMemsetAsync(pS2, 0, sizeof(float) * NREL * NNODES * 16);
    cudaMemsetAsync(pS3, 0, sizeof(float) * NREL * NNODES * 32);
    cudaMemsetAsync(pcnt, 0, sizeof(int) * NREL * NNODES);

    const int TB = 256;

    // smem sizes (bytes): weights + NPB*(5*DIN+4) floats
    // L1: DIN16 DOUT16 SPLIT2 NT1 -> NPB=128: 5120 + 43008 = 48128
    // L2: DIN16 DOUT32 SPLIT4 NT2 -> NPB=128: 10240 + 43008 = 53248
    // L3: DIN32 DOUT64 SPLIT8 NT2 -> NPB=64 : 40960 + 41984 = 82944
    const int smem1 = (5*16*16 + 128*(5*16+4)) * 4;
    const int smem2 = (5*16*32 + 128*(5*16+4)) * 4;
    const int smem3 = (5*32*64 + 64*(5*32+4)) * 4;

    static bool attr_done = false;
    if (!attr_done) {
        cudaFuncSetAttribute(combine_kernel<16, 32, 4, 2, true>,
                             cudaFuncAttributeMaxDynamicSharedMemorySize, smem2);
        cudaFuncSetAttribute(combine_kernel<32, 64, 8, 2, false>,
                             cudaFuncAttributeMaxDynamicSharedMemorySize, smem3);
        attr_done = true;
    }

    // Layer 1: 16 -> 16, relu (scatter fuses degree count)
    {
        int tot = e * 4;
        scatter_kernel<16, true><<<(tot + TB - 1) / TB, TB>>>(
            x, src, dst, et, pS1, pcnt, n, e);
        int tiles = (n + 127) / 128;
        int grid = tiles < 444 ? tiles : 444;
        combine_kernel<16, 16, 2, 1, true><<<grid, 256, smem1>>>(
            x, pS1, pcnt, W1, root1, b1, ph1, n, tiles);
    }

    // Layer 2: 16 -> 32, relu
    {
        int tot = e * 4;
        scatter_kernel<16, false><<<(tot + TB - 1) / TB, TB>>>(
            ph1, src, dst, et, pS2, pcnt, n, e);
        int tiles = (n + 127) / 128;
        int grid = tiles < 444 ? tiles : 444;
        combine_kernel<16, 32, 4, 2, true><<<grid, 256, smem2>>>(
            ph1, pS2, pcnt, W2, root2, b2, ph2, n, tiles);
    }

    // Layer 3: 32 -> 64, no relu
    {
        int tot = e * 8;
        scatter_kernel<32, false><<<(tot + TB - 1) / TB, TB>>>(
            ph2, src, dst, et, pS3, pcnt, n, e);
        int tiles = (n + 63) / 64;
        int grid = tiles < 296 ? tiles : 296;
        combine_kernel<32, 64, 8, 2, false><<<grid, 256, smem3>>>(
            ph2, pS3, pcnt, W3, root3, b3, out, n, tiles);
    }
}